// round 2
// baseline (speedup 1.0000x reference)
#include <cuda_runtime.h>
#include <math.h>

// Problem constants (fixed by the dataset)
#define MAXN 40000
#define MAXE 640000
#define D 128
#define H 4
#define C 32
#define NEG_SLOPE 0.2f

// -------- device scratch (static; no allocation allowed) --------
__device__ float g_xv_node[MAXN * D];   // x' @ Wv^T per node   (20.5 MB)
__device__ float g_ai[MAXN * H];        // (xq . att_i) per node,head
__device__ float g_aj[MAXN * H];        // (xk_node . att_j) per node,head
__device__ float g_denom[MAXN * H];     // softmax denominators
__device__ float g_WvT[D * D];          // Wv transposed for coalesced access
__device__ float g_qvec[H * D];         // q_vec[h,d] = sum_c Wq[hC+c,d]*att_i[h,c]
__device__ float g_kvec[H * D];         // k_vec[h,d] = sum_c Wk[hC+c,d]*att_j[h,c]
__device__ float g_xv_edge[8 * D];      // edge_emb_table @ Wv^T
__device__ float g_aj_edge[8 * H];      // edge_emb_table . k_vec

// -------- tiny precompute: fold attention vectors through W --------
__global__ void precompute_kernel(const float* __restrict__ Wq,
                                  const float* __restrict__ Wk,
                                  const float* __restrict__ Wv,
                                  const float* __restrict__ att_i,
                                  const float* __restrict__ att_j,
                                  const float* __restrict__ edge_emb) {
    int t = threadIdx.x;  // 512 threads, 1 block
    if (t < H * D) {
        int h = t >> 7, d = t & 127;
        float q = 0.f, k = 0.f;
        #pragma unroll
        for (int c = 0; c < C; c++) {
            q = fmaf(Wq[(h * C + c) * D + d], att_i[h * C + c], q);
            k = fmaf(Wk[(h * C + c) * D + d], att_j[h * C + c], k);
        }
        g_qvec[h * D + d] = q;
        g_kvec[h * D + d] = k;
    }
    for (int i = t; i < D * D; i += 512) {
        int d = i >> 7, o = i & 127;
        g_WvT[i] = Wv[o * D + d];
    }
    for (int i = t; i < 8 * D; i += 512) {
        int et = i >> 7, o = i & 127;
        float s = 0.f;
        for (int dd = 0; dd < D; dd++)
            s = fmaf(Wv[o * D + dd], edge_emb[et * D + dd], s);
        g_xv_edge[i] = s;
    }
    __syncthreads();
    if (t < 8 * H) {
        int et = t >> 2, h = t & 3;
        float s = 0.f;
        for (int dd = 0; dd < D; dd++)
            s = fmaf(edge_emb[et * D + dd], g_kvec[h * D + dd], s);
        g_aj_edge[t] = s;
    }
}

// -------- zero output accumulator + denominators --------
__global__ void init_kernel(float* __restrict__ out, int N) {
    int i = blockIdx.x * blockDim.x + threadIdx.x;
    if (i < N * D) out[i] = 0.f;
    if (i < N * H) g_denom[i] = 0.f;
}

// -------- per-node: x' = x + node_emb[nt]; xv_node = x'@Wv^T; a_i, aj --------
// blockDim = 128, 16 nodes per block
__global__ void node_kernel(const float* __restrict__ x,
                            const int* __restrict__ node_type,
                            const float* __restrict__ node_emb,
                            int N) {
    __shared__ float xs[16][D];
    int t = threadIdx.x;
    int base = blockIdx.x * 16;
    #pragma unroll
    for (int m = 0; m < 16; m++) {
        int n = base + m;
        if (n < N) {
            int nt = __ldg(&node_type[n]);
            xs[m][t] = x[(size_t)n * D + t] + __ldg(&node_emb[nt * D + t]);
        } else {
            xs[m][t] = 0.f;
        }
    }
    __syncthreads();

    float acc[16];
    #pragma unroll
    for (int m = 0; m < 16; m++) acc[m] = 0.f;
    for (int d = 0; d < D; d++) {
        float w = g_WvT[d * D + t];     // coalesced across threads
        #pragma unroll
        for (int m = 0; m < 16; m++)
            acc[m] = fmaf(xs[m][d], w, acc[m]);  // smem broadcast
    }
    #pragma unroll
    for (int m = 0; m < 16; m++) {
        int n = base + m;
        if (n < N) g_xv_node[(size_t)n * D + t] = acc[m];
    }

    // a_i / aj scalars: 64 threads, one (node,head) each
    if (t < 64) {
        int m = t >> 2, h = t & 3;
        int n = base + m;
        if (n < N) {
            float ai = 0.f, aj = 0.f;
            for (int d = 0; d < D; d++) {
                float xv = xs[m][d];
                ai = fmaf(xv, g_qvec[h * D + d], ai);
                aj = fmaf(xv, g_kvec[h * D + d], aj);
            }
            g_ai[n * H + h] = ai;
            g_aj[n * H + h] = aj;
        }
    }
}

// -------- single edge pass: alpha -> exp -> scatter denom + weighted values --------
// one warp per edge (E real edges + N self-loops)
__global__ void edge_kernel(const int* __restrict__ ei,       // [2,E] src then dst
                            const int* __restrict__ edge_type,
                            float* __restrict__ out,
                            int E, int N) {
    int gw = (blockIdx.x * blockDim.x + threadIdx.x) >> 5;
    int lane = threadIdx.x & 31;
    int Etot = E + N;
    if (gw >= Etot) return;

    int src, dst, et;
    if (gw < E) {
        src = __ldg(&ei[gw]);
        dst = __ldg(&ei[E + gw]);
        et  = __ldg(&edge_type[gw]);
    } else {
        src = dst = gw - E;
        et = 0;  // EDGE_TYPE_SELF
    }

    // head for this lane's 4-float chunk: c = 4*lane -> h = lane/8
    int h = lane >> 3;
    float ah = __ldg(&g_ai[dst * H + h]) + __ldg(&g_aj[src * H + h])
             + g_aj_edge[et * H + h];
    ah = ah > 0.f ? ah : NEG_SLOPE * ah;
    float w = expf(ah);

    // denominators: lanes 0..3 handle head = lane
    if (lane < H) {
        float a2 = __ldg(&g_ai[dst * H + lane]) + __ldg(&g_aj[src * H + lane])
                 + g_aj_edge[et * H + lane];
        a2 = a2 > 0.f ? a2 : NEG_SLOPE * a2;
        atomicAdd(&g_denom[dst * H + lane], expf(a2));
    }

    // weighted value scatter: xv = xv_node[src] + xv_edge[et], 4 floats/lane
    const float4* vn = reinterpret_cast<const float4*>(&g_xv_node[(size_t)src * D]);
    const float4* ve = reinterpret_cast<const float4*>(&g_xv_edge[et * D]);
    float4 a = vn[lane];
    float4 b = ve[lane];
    float4 r;
    r.x = w * (a.x + b.x);
    r.y = w * (a.y + b.y);
    r.z = w * (a.z + b.z);
    r.w = w * (a.w + b.w);
    float* dp = out + (size_t)dst * D + lane * 4;
    asm volatile("red.global.add.v4.f32 [%0], {%1, %2, %3, %4};"
                 :: "l"(dp), "f"(r.x), "f"(r.y), "f"(r.z), "f"(r.w)
                 : "memory");
}

// -------- normalize + bias --------
__global__ void finalize_kernel(float* __restrict__ out,
                                const float* __restrict__ bias,
                                int N) {
    int i = blockIdx.x * blockDim.x + threadIdx.x;
    if (i < N * D) {
        int n = i >> 7;
        int c = i & 127;
        int h = c >> 5;
        out[i] = out[i] / (g_denom[n * H + h] + 1e-16f) + __ldg(&bias[c]);
    }
}

extern "C" void kernel_launch(void* const* d_in, const int* in_sizes, int n_in,
                              void* d_out, int out_size) {
    const float* x         = (const float*)d_in[0];
    const int*   ei        = (const int*)  d_in[1];   // [2,E]
    const int*   node_type = (const int*)  d_in[2];
    const int*   edge_type = (const int*)  d_in[3];
    const float* Wq        = (const float*)d_in[4];
    const float* Wk        = (const float*)d_in[5];
    const float* Wv        = (const float*)d_in[6];
    const float* att_i     = (const float*)d_in[7];
    const float* att_j     = (const float*)d_in[8];
    const float* bias      = (const float*)d_in[9];
    const float* node_emb  = (const float*)d_in[10];
    const float* edge_emb  = (const float*)d_in[11];
    float* out = (float*)d_out;

    int N = in_sizes[2];          // node_type count = 40000
    int E = in_sizes[3];          // edge_type count = 640000

    precompute_kernel<<<1, 512>>>(Wq, Wk, Wv, att_i, att_j, edge_emb);
    init_kernel<<<(N * D + 255) / 256, 256>>>(out, N);
    node_kernel<<<(N + 15) / 16, 128>>>(x, node_type, node_emb, N);
    int Etot = E + N;
    edge_kernel<<<(Etot + 7) / 8, 256>>>(ei, edge_type, out, E, N);
    finalize_kernel<<<(N * D + 255) / 256, 256>>>(out, bias, N);
}

// round 4
// speedup vs baseline: 1.0763x; 1.0763x over previous
#include <cuda_runtime.h>
#include <cuda_fp16.h>
#include <math.h>

#define MAXN 40000
#define MAXE 640000
#define D 128
#define H 4
#define C 32
#define NEG_SLOPE 0.2f

// -------- device scratch (static; no allocation allowed) --------
__device__ __half g_xvh[(size_t)MAXN * D];   // x' @ Wv^T per node (fp16, 10.2 MB)
__device__ float g_ai[MAXN * H];             // (xq . att_i) per node,head
__device__ float g_aj[MAXN * H];             // (xk_node . att_j) per node,head
__device__ float g_WvT[D * D];               // Wv transposed
__device__ float g_qvec[H * D];
__device__ float g_kvec[H * D];
__device__ float g_xv_edge[8 * D];           // edge_emb_table @ Wv^T
__device__ float g_aj_edge[8 * H];           // edge_emb_table . k_vec
__device__ int   g_deg[MAXN];
__device__ int   g_rowstart[MAXN + 1];
__device__ int   g_cursor[MAXN];
__device__ int   g_adj[MAXE];                // src | (et<<24)

// ---- f32x2 helpers (sm_103a packed fp32 FMA: 2x FFMA rate, full precision) ----
__device__ __forceinline__ unsigned long long pack2(float x, float y) {
    unsigned long long r;
    asm("mov.b64 %0, {%1, %2};" : "=l"(r) : "f"(x), "f"(y));
    return r;
}
__device__ __forceinline__ void unpack2(unsigned long long v, float& x, float& y) {
    asm("mov.b64 {%0, %1}, %2;" : "=f"(x), "=f"(y) : "l"(v));
}
__device__ __forceinline__ void fma2(unsigned long long& acc, unsigned long long a,
                                     unsigned long long b) {
    asm("fma.rn.f32x2 %0, %1, %2, %0;" : "+l"(acc) : "l"(a), "l"(b));
}

__device__ __forceinline__ float4 h4_to_f4(uint2 u) {
    __half2 a = *reinterpret_cast<__half2*>(&u.x);
    __half2 b = *reinterpret_cast<__half2*>(&u.y);
    float2 fa = __half22float2(a);
    float2 fb = __half22float2(b);
    return make_float4(fa.x, fa.y, fb.x, fb.y);
}

// -------- tiny precompute: fold attention vectors through W --------
__global__ void precompute_kernel(const float* __restrict__ Wq,
                                  const float* __restrict__ Wk,
                                  const float* __restrict__ Wv,
                                  const float* __restrict__ att_i,
                                  const float* __restrict__ att_j,
                                  const float* __restrict__ edge_emb) {
    int t = threadIdx.x;  // 512 threads, 1 block
    if (t < H * D) {
        int h = t >> 7, d = t & 127;
        float q = 0.f, k = 0.f;
        #pragma unroll
        for (int c = 0; c < C; c++) {
            q = fmaf(Wq[(h * C + c) * D + d], att_i[h * C + c], q);
            k = fmaf(Wk[(h * C + c) * D + d], att_j[h * C + c], k);
        }
        g_qvec[h * D + d] = q;
        g_kvec[h * D + d] = k;
    }
    for (int i = t; i < D * D; i += 512) {
        int d = i >> 7, o = i & 127;
        g_WvT[i] = Wv[o * D + d];
    }
    for (int i = t; i < 8 * D; i += 512) {
        int et = i >> 7, o = i & 127;
        float s = 0.f;
        for (int dd = 0; dd < D; dd++)
            s = fmaf(Wv[o * D + dd], edge_emb[et * D + dd], s);
        g_xv_edge[i] = s;
    }
    __syncthreads();
    if (t < 8 * H) {
        int et = t >> 2, h = t & 3;
        float s = 0.f;
        for (int dd = 0; dd < D; dd++)
            s = fmaf(edge_emb[et * D + dd], g_kvec[h * D + dd], s);
        g_aj_edge[t] = s;
    }
}

// -------- CSR build --------
__global__ void zero_kernel(int N) {
    int i = blockIdx.x * blockDim.x + threadIdx.x;
    if (i < N) g_deg[i] = 0;
}

__global__ void hist_kernel(const int* __restrict__ ei, int E) {
    int e = blockIdx.x * blockDim.x + threadIdx.x;
    if (e < E) atomicAdd(&g_deg[__ldg(&ei[E + e])], 1);
}

__global__ void scan_kernel(int N) {
    __shared__ int wsum[32];
    __shared__ int s_total;
    int t = threadIdx.x;  // 1024
    int lane = t & 31, wid = t >> 5;
    if (t == 0) s_total = 0;
    __syncthreads();
    for (int chunk = 0; chunk < N; chunk += 1024) {
        int idx = chunk + t;
        int v = (idx < N) ? g_deg[idx] : 0;
        int s = v;
        #pragma unroll
        for (int o = 1; o < 32; o <<= 1) {
            int y = __shfl_up_sync(0xFFFFFFFFu, s, o);
            if (lane >= o) s += y;
        }
        if (lane == 31) wsum[wid] = s;
        __syncthreads();
        if (wid == 0) {
            int ws = wsum[lane];
            #pragma unroll
            for (int o = 1; o < 32; o <<= 1) {
                int y = __shfl_up_sync(0xFFFFFFFFu, ws, o);
                if (lane >= o) ws += y;
            }
            wsum[lane] = ws;
        }
        __syncthreads();
        int base = s_total + (wid > 0 ? wsum[wid - 1] : 0);
        int excl = base + s - v;
        if (idx < N) {
            g_rowstart[idx] = excl;
            g_cursor[idx] = excl;
        }
        __syncthreads();
        if (t == 0) s_total += wsum[31];
        __syncthreads();
    }
    if (t == 0) g_rowstart[N] = s_total;
}

__global__ void scatter_kernel(const int* __restrict__ ei,
                               const int* __restrict__ edge_type, int E) {
    int e = blockIdx.x * blockDim.x + threadIdx.x;
    if (e < E) {
        int src = __ldg(&ei[e]);
        int dst = __ldg(&ei[E + e]);
        int et  = __ldg(&edge_type[e]);
        int pos = atomicAdd(&g_cursor[dst], 1);
        g_adj[pos] = src | (et << 24);
    }
}

// -------- per-node: x' = x + emb; xv = x'@Wv^T (f32x2 GEMM, fp16 out); ai/aj --------
#define MTILE 16
__global__ void node_kernel(const float* __restrict__ x,
                            const int* __restrict__ node_type,
                            const float* __restrict__ node_emb, int N) {
    __shared__ float xs[D * 18];  // transposed [d][m], pad 18 (8B-aligned rows)
    int t = threadIdx.x;          // 128
    int base = blockIdx.x * MTILE;
    #pragma unroll
    for (int m = 0; m < MTILE; m++) {
        int n = base + m;
        float val = 0.f;
        if (n < N) {
            int nt = __ldg(&node_type[n]);
            val = __ldg(&x[(size_t)n * D + t]) + __ldg(&node_emb[nt * D + t]);
        }
        xs[t * 18 + m] = val;
    }
    __syncthreads();

    unsigned long long acc2[8];
    #pragma unroll
    for (int i = 0; i < 8; i++) acc2[i] = pack2(0.f, 0.f);

    #pragma unroll 4
    for (int d = 0; d < D; d++) {
        float w = g_WvT[d * D + t];
        unsigned long long ww = pack2(w, w);
        const float2* xr = reinterpret_cast<const float2*>(&xs[d * 18]);
        #pragma unroll
        for (int i = 0; i < 8; i++) {
            float2 xp = xr[i];
            unsigned long long xp2 = *reinterpret_cast<unsigned long long*>(&xp);
            fma2(acc2[i], xp2, ww);
        }
    }
    #pragma unroll
    for (int i = 0; i < 8; i++) {
        float lo, hi;
        unpack2(acc2[i], lo, hi);
        int n0 = base + 2 * i;
        if (n0 < N)     g_xvh[(size_t)n0 * D + t]       = __float2half(lo);
        if (n0 + 1 < N) g_xvh[(size_t)(n0 + 1) * D + t] = __float2half(hi);
    }

    // attention scalars: 64 threads, one (node,head) each
    if (t < 64) {
        int m = t >> 2, h = t & 3;
        int n = base + m;
        if (n < N) {
            float ai = 0.f, aj = 0.f;
            for (int d = 0; d < D; d++) {
                float xv = xs[d * 18 + m];
                ai = fmaf(xv, g_qvec[h * D + d], ai);
                aj = fmaf(xv, g_kvec[h * D + d], aj);
            }
            g_ai[n * H + h] = ai;
            g_aj[n * H + h] = aj;
        }
    }
}

// -------- gather: one warp per dst node, register accumulation, no atomics --------
__global__ void gather_kernel(float* __restrict__ out,
                              const float* __restrict__ bias, int N) {
    __shared__ float s_xve[8 * D];
    __shared__ float s_aje[8 * H];
    int tid = threadIdx.x;
    for (int i = tid; i < 8 * D; i += blockDim.x) s_xve[i] = g_xv_edge[i];
    if (tid < 32) s_aje[tid] = g_aj_edge[tid];
    __syncthreads();

    int n = (blockIdx.x * blockDim.x + tid) >> 5;
    int lane = tid & 31;
    if (n >= N) return;
    int h = lane >> 3;

    float ai_h = __ldg(&g_ai[n * H + h]);

    // self-loop (edge type 0)
    float a = ai_h + __ldg(&g_aj[n * H + h]) + s_aje[h];
    a = fmaxf(a, NEG_SLOPE * a);
    float w = __expf(a);
    float denom = w;
    uint2 hv = __ldg(reinterpret_cast<const uint2*>(g_xvh + (size_t)n * D) + lane);
    float4 v = h4_to_f4(hv);
    float4 ev = *reinterpret_cast<const float4*>(&s_xve[lane * 4]);
    float4 acc;
    acc.x = w * (v.x + ev.x);
    acc.y = w * (v.y + ev.y);
    acc.z = w * (v.z + ev.z);
    acc.w = w * (v.w + ev.w);

    int row0 = __ldg(&g_rowstart[n]);
    int row1 = __ldg(&g_rowstart[n + 1]);
    for (int bs = row0; bs < row1; bs += 32) {
        int rem = row1 - bs;
        int cnt = min(rem, 32);
        int p = (lane < cnt) ? __ldg(&g_adj[bs + lane]) : 0;
        int j = 0;
        for (; j + 1 < cnt; j += 2) {
            int p0 = __shfl_sync(0xFFFFFFFFu, p, j);
            int p1 = __shfl_sync(0xFFFFFFFFu, p, j + 1);
            int s0 = p0 & 0xFFFFFF, e0 = p0 >> 24;
            int s1 = p1 & 0xFFFFFF, e1 = p1 >> 24;
            float aj0 = __ldg(&g_aj[s0 * H + h]);
            float aj1 = __ldg(&g_aj[s1 * H + h]);
            uint2 h0 = __ldg(reinterpret_cast<const uint2*>(g_xvh + (size_t)s0 * D) + lane);
            uint2 h1 = __ldg(reinterpret_cast<const uint2*>(g_xvh + (size_t)s1 * D) + lane);
            float a0 = ai_h + aj0 + s_aje[e0 * H + h];
            a0 = fmaxf(a0, NEG_SLOPE * a0);
            float w0 = __expf(a0);
            float a1 = ai_h + aj1 + s_aje[e1 * H + h];
            a1 = fmaxf(a1, NEG_SLOPE * a1);
            float w1 = __expf(a1);
            denom += w0;
            denom += w1;
            float4 v0 = h4_to_f4(h0);
            float4 v1 = h4_to_f4(h1);
            const float4 ee0 = *reinterpret_cast<const float4*>(&s_xve[e0 * D + lane * 4]);
            const float4 ee1 = *reinterpret_cast<const float4*>(&s_xve[e1 * D + lane * 4]);
            acc.x = fmaf(w0, v0.x + ee0.x, acc.x);
            acc.y = fmaf(w0, v0.y + ee0.y, acc.y);
            acc.z = fmaf(w0, v0.z + ee0.z, acc.z);
            acc.w = fmaf(w0, v0.w + ee0.w, acc.w);
            acc.x = fmaf(w1, v1.x + ee1.x, acc.x);
            acc.y = fmaf(w1, v1.y + ee1.y, acc.y);
            acc.z = fmaf(w1, v1.z + ee1.z, acc.z);
            acc.w = fmaf(w1, v1.w + ee1.w, acc.w);
        }
        if (j < cnt) {
            int p0 = __shfl_sync(0xFFFFFFFFu, p, j);
            int s0 = p0 & 0xFFFFFF, e0 = p0 >> 24;
            float aj0 = __ldg(&g_aj[s0 * H + h]);
            uint2 h0 = __ldg(reinterpret_cast<const uint2*>(g_xvh + (size_t)s0 * D) + lane);
            float a0 = ai_h + aj0 + s_aje[e0 * H + h];
            a0 = fmaxf(a0, NEG_SLOPE * a0);
            float w0 = __expf(a0);
            denom += w0;
            float4 v0 = h4_to_f4(h0);
            const float4 ee0 = *reinterpret_cast<const float4*>(&s_xve[e0 * D + lane * 4]);
            acc.x = fmaf(w0, v0.x + ee0.x, acc.x);
            acc.y = fmaf(w0, v0.y + ee0.y, acc.y);
            acc.z = fmaf(w0, v0.z + ee0.z, acc.z);
            acc.w = fmaf(w0, v0.w + ee0.w, acc.w);
        }
    }

    float inv = 1.f / (denom + 1e-16f);
    float4 b4 = __ldg(reinterpret_cast<const float4*>(bias) + lane);
    float4 r;
    r.x = fmaf(acc.x, inv, b4.x);
    r.y = fmaf(acc.y, inv, b4.y);
    r.z = fmaf(acc.z, inv, b4.z);
    r.w = fmaf(acc.w, inv, b4.w);
    reinterpret_cast<float4*>(out + (size_t)n * D)[lane] = r;
}

extern "C" void kernel_launch(void* const* d_in, const int* in_sizes, int n_in,
                              void* d_out, int out_size) {
    const float* x         = (const float*)d_in[0];
    const int*   ei        = (const int*)  d_in[1];   // [2,E]
    const int*   node_type = (const int*)  d_in[2];
    const int*   edge_type = (const int*)  d_in[3];
    const float* Wq        = (const float*)d_in[4];
    const float* Wk        = (const float*)d_in[5];
    const float* Wv        = (const float*)d_in[6];
    const float* att_i     = (const float*)d_in[7];
    const float* att_j     = (const float*)d_in[8];
    const float* bias      = (const float*)d_in[9];
    const float* node_emb  = (const float*)d_in[10];
    const float* edge_emb  = (const float*)d_in[11];
    float* out = (float*)d_out;

    int N = in_sizes[2];
    int E = in_sizes[3];

    zero_kernel<<<(N + 255) / 256, 256>>>(N);
    precompute_kernel<<<1, 512>>>(Wq, Wk, Wv, att_i, att_j, edge_emb);
    hist_kernel<<<(E + 255) / 256, 256>>>(ei, E);
    scan_kernel<<<1, 1024>>>(N);
    scatter_kernel<<<(E + 255) / 256, 256>>>(ei, edge_type, E);
    node_kernel<<<(N + MTILE - 1) / MTILE, 128>>>(x, node_type, node_emb, N);
    gather_kernel<<<(N * 32 + 255) / 256, 256>>>(out, bias, N);
}

// round 8
// speedup vs baseline: 1.7358x; 1.6127x over previous
#include <cuda_runtime.h>
#include <cuda_fp16.h>
#include <math.h>

#define MAXN 40000
#define MAXE 640000
#define D 128
#define H 4
#define C 32
#define NEG_SLOPE 0.2f
#define SCAN_BLK 512

// -------- device scratch (static; no allocation allowed) --------
__device__ __half g_xvh[(size_t)MAXN * D];   // x' @ Wv^T per node (fp16, 10.2 MB)
__device__ float g_ai[MAXN * H];
__device__ float g_aj[MAXN * H];
__device__ float g_WvT[D * D];
__device__ float g_qvec[H * D];
__device__ float g_kvec[H * D];
__device__ float g_xv_edge[8 * D];
__device__ float g_aj_edge[8 * H];
__device__ int   g_deg[MAXN];
__device__ int   g_rowstart[MAXN + 1];
__device__ int   g_cursor[MAXN];
__device__ int   g_adj[MAXE];                // src | (et<<24)
__device__ int   g_bsum[256];
__device__ int   g_boff[256];

// ---- f32x2 helpers (sm_103a packed fp32 FMA) ----
__device__ __forceinline__ unsigned long long pack2(float x, float y) {
    unsigned long long r;
    asm("mov.b64 %0, {%1, %2};" : "=l"(r) : "f"(x), "f"(y));
    return r;
}
__device__ __forceinline__ void unpack2(unsigned long long v, float& x, float& y) {
    asm("mov.b64 {%0, %1}, %2;" : "=f"(x), "=f"(y) : "l"(v));
}
__device__ __forceinline__ void fma2(unsigned long long& acc, unsigned long long a,
                                     unsigned long long b) {
    asm("fma.rn.f32x2 %0, %1, %2, %0;" : "+l"(acc) : "l"(a), "l"(b));
}
__device__ __forceinline__ float4 h4_to_f4(uint2 u) {
    __half2 a = *reinterpret_cast<__half2*>(&u.x);
    __half2 b = *reinterpret_cast<__half2*>(&u.y);
    float2 fa = __half22float2(a);
    float2 fb = __half22float2(b);
    return make_float4(fa.x, fa.y, fb.x, fb.y);
}

// -------- widened precompute: grid = 140 blocks x 128 threads --------
__global__ void precompute_kernel(const float* __restrict__ Wq,
                                  const float* __restrict__ Wk,
                                  const float* __restrict__ Wv,
                                  const float* __restrict__ att_i,
                                  const float* __restrict__ att_j,
                                  const float* __restrict__ edge_emb) {
    int b = blockIdx.x, t = threadIdx.x;
    if (b < 4) {
        // head b: fold attention through Wq/Wk, then aj_edge reductions
        int h = b, d = t;
        float q = 0.f, k = 0.f;
        #pragma unroll
        for (int c = 0; c < C; c++) {
            q = fmaf(__ldg(&Wq[(h * C + c) * D + d]), __ldg(&att_i[h * C + c]), q);
            k = fmaf(__ldg(&Wk[(h * C + c) * D + d]), __ldg(&att_j[h * C + c]), k);
        }
        g_qvec[h * D + d] = q;
        g_kvec[h * D + d] = k;
        __shared__ float red[D];
        for (int et = 0; et < 8; et++) {
            red[t] = __ldg(&edge_emb[et * D + t]) * k;
            __syncthreads();
            for (int s = 64; s > 0; s >>= 1) {
                if (t < s) red[t] += red[t + s];
                __syncthreads();
            }
            if (t == 0) g_aj_edge[et * H + h] = red[0];
            __syncthreads();
        }
    } else if (b < 12) {
        // xv_edge row for edge type (b-4): out channel t
        int et = b - 4;
        float s = 0.f;
        for (int dd = 0; dd < D; dd++)
            s = fmaf(__ldg(&Wv[t * D + dd]), __ldg(&edge_emb[et * D + dd]), s);
        g_xv_edge[et * D + t] = s;
    } else {
        // transpose Wv: blocks 12..139 each handle 128 elements
        int i = (b - 12) * 128 + t;
        int d = i >> 7, o = i & 127;
        g_WvT[i] = __ldg(&Wv[o * D + d]);
    }
}

// -------- CSR build --------
__global__ void zero_kernel(int N) {
    int i = blockIdx.x * blockDim.x + threadIdx.x;
    if (i < N) g_deg[i] = 0;
}

__global__ void hist_kernel(const int* __restrict__ ei, int E) {
    int e = blockIdx.x * blockDim.x + threadIdx.x;
    if (e < E) atomicAdd(&g_deg[__ldg(&ei[E + e])], 1);
}

// phase 1: per-block local scan + block sums
// NOTE: the warp-level scan of the 16 warp-sums is executed by ALL 32 lanes
// of warp 0 (inactive lanes carry 0) — a partial-warp __shfl_up_sync with a
// full mask is UB and hung the previous two rounds.
__global__ void scan1_kernel(int N) {
    __shared__ int ws[SCAN_BLK / 32];
    int t = threadIdx.x, lane = t & 31, wid = t >> 5;
    int idx = blockIdx.x * SCAN_BLK + t;
    int v = (idx < N) ? g_deg[idx] : 0;
    int s = v;
    #pragma unroll
    for (int o = 1; o < 32; o <<= 1) {
        int y = __shfl_up_sync(0xFFFFFFFFu, s, o);
        if (lane >= o) s += y;
    }
    if (lane == 31) ws[wid] = s;
    __syncthreads();
    if (wid == 0) {
        int wv = (lane < SCAN_BLK / 32) ? ws[lane] : 0;
        #pragma unroll
        for (int o = 1; o < SCAN_BLK / 32; o <<= 1) {
            int y = __shfl_up_sync(0xFFFFFFFFu, wv, o);
            if (lane >= o) wv += y;
        }
        if (lane < SCAN_BLK / 32) ws[lane] = wv;
    }
    __syncthreads();
    int base = (wid > 0) ? ws[wid - 1] : 0;
    if (idx < N) g_rowstart[idx] = base + s - v;
    if (t == 0) g_bsum[blockIdx.x] = ws[SCAN_BLK / 32 - 1];
}

// phase 2: scan the (<=256) block sums (no intra-warp divergence before shuffles)
__global__ void scan2_kernel(int nb, int N) {
    __shared__ int ws[8];
    int t = threadIdx.x, lane = t & 31, wid = t >> 5;  // 256 threads
    int v = (t < nb) ? g_bsum[t] : 0;
    int s = v;
    #pragma unroll
    for (int o = 1; o < 32; o <<= 1) {
        int y = __shfl_up_sync(0xFFFFFFFFu, s, o);
        if (lane >= o) s += y;
    }
    if (lane == 31) ws[wid] = s;
    __syncthreads();
    int add = 0;
    for (int w = 0; w < wid; w++) add += ws[w];
    s += add;
    if (t < nb) g_boff[t] = s - v;
    if (t == nb - 1) g_rowstart[N] = s;
}

// phase 3: add block offsets, init cursor
__global__ void scan3_kernel(int N) {
    int idx = blockIdx.x * SCAN_BLK + threadIdx.x;
    if (idx < N) {
        int r = g_rowstart[idx] + g_boff[blockIdx.x];
        g_rowstart[idx] = r;
        g_cursor[idx] = r;
    }
}

__global__ void scatter_kernel(const int* __restrict__ ei,
                               const int* __restrict__ edge_type, int E) {
    int e = blockIdx.x * blockDim.x + threadIdx.x;
    if (e < E) {
        int src = __ldg(&ei[e]);
        int dst = __ldg(&ei[E + e]);
        int et  = __ldg(&edge_type[e]);
        int pos = atomicAdd(&g_cursor[dst], 1);
        g_adj[pos] = src | (et << 24);
    }
}

// -------- per-node: x' = x + emb; xv = x'@Wv^T (f32x2); ai/aj --------
#define MTILE 16
__global__ void node_kernel(const float* __restrict__ x,
                            const int* __restrict__ node_type,
                            const float* __restrict__ node_emb, int N) {
    __shared__ float xs[D * 18];
    int t = threadIdx.x;          // 128
    int base = blockIdx.x * MTILE;
    #pragma unroll
    for (int m = 0; m < MTILE; m++) {
        int n = base + m;
        float val = 0.f;
        if (n < N) {
            int nt = __ldg(&node_type[n]);
            val = __ldg(&x[(size_t)n * D + t]) + __ldg(&node_emb[nt * D + t]);
        }
        xs[t * 18 + m] = val;
    }
    __syncthreads();

    unsigned long long acc2[8];
    #pragma unroll
    for (int i = 0; i < 8; i++) acc2[i] = pack2(0.f, 0.f);

    #pragma unroll 4
    for (int d = 0; d < D; d++) {
        float w = g_WvT[d * D + t];
        unsigned long long ww = pack2(w, w);
        const float2* xr = reinterpret_cast<const float2*>(&xs[d * 18]);
        #pragma unroll
        for (int i = 0; i < 8; i++) {
            float2 xp = xr[i];
            unsigned long long xp2 = *reinterpret_cast<unsigned long long*>(&xp);
            fma2(acc2[i], xp2, ww);
        }
    }
    #pragma unroll
    for (int i = 0; i < 8; i++) {
        float lo, hi;
        unpack2(acc2[i], lo, hi);
        int n0 = base + 2 * i;
        if (n0 < N)     g_xvh[(size_t)n0 * D + t]       = __float2half(lo);
        if (n0 + 1 < N) g_xvh[(size_t)(n0 + 1) * D + t] = __float2half(hi);
    }

    if (t < 64) {
        int m = t >> 2, h = t & 3;
        int n = base + m;
        if (n < N) {
            float ai = 0.f, aj = 0.f;
            for (int d = 0; d < D; d++) {
                float xv = xs[d * 18 + m];
                ai = fmaf(xv, g_qvec[h * D + d], ai);
                aj = fmaf(xv, g_kvec[h * D + d], aj);
            }
            g_ai[n * H + h] = ai;
            g_aj[n * H + h] = aj;
        }
    }
}

// -------- gather: one warp per dst node, register accumulation --------
__global__ void gather_kernel(float* __restrict__ out,
                              const float* __restrict__ bias, int N) {
    __shared__ float s_xve[8 * D];
    __shared__ float s_aje[8 * H];
    int tid = threadIdx.x;
    for (int i = tid; i < 8 * D; i += blockDim.x) s_xve[i] = g_xv_edge[i];
    if (tid < 32) s_aje[tid] = g_aj_edge[tid];
    __syncthreads();

    int n = (blockIdx.x * blockDim.x + tid) >> 5;
    int lane = tid & 31;
    if (n >= N) return;
    int h = lane >> 3;

    float ai_h = __ldg(&g_ai[n * H + h]);

    // self-loop (edge type 0)
    float a = ai_h + __ldg(&g_aj[n * H + h]) + s_aje[h];
    a = fmaxf(a, NEG_SLOPE * a);
    float w = __expf(a);
    float denom = w;
    uint2 hv = __ldg(reinterpret_cast<const uint2*>(g_xvh + (size_t)n * D) + lane);
    float4 v = h4_to_f4(hv);
    float4 ev = *reinterpret_cast<const float4*>(&s_xve[lane * 4]);
    float4 acc;
    acc.x = w * (v.x + ev.x);
    acc.y = w * (v.y + ev.y);
    acc.z = w * (v.z + ev.z);
    acc.w = w * (v.w + ev.w);

    int row0 = __ldg(&g_rowstart[n]);
    int row1 = __ldg(&g_rowstart[n + 1]);
    for (int bs = row0; bs < row1; bs += 32) {
        int rem = row1 - bs;
        int cnt = min(rem, 32);
        int p = (lane < cnt) ? __ldg(&g_adj[bs + lane]) : 0;
        int j = 0;
        for (; j + 1 < cnt; j += 2) {
            int p0 = __shfl_sync(0xFFFFFFFFu, p, j);
            int p1 = __shfl_sync(0xFFFFFFFFu, p, j + 1);
            int s0 = p0 & 0xFFFFFF, e0 = p0 >> 24;
            int s1 = p1 & 0xFFFFFF, e1 = p1 >> 24;
            float aj0 = __ldg(&g_aj[s0 * H + h]);
            float aj1 = __ldg(&g_aj[s1 * H + h]);
            uint2 h0 = __ldg(reinterpret_cast<const uint2*>(g_xvh + (size_t)s0 * D) + lane);
            uint2 h1 = __ldg(reinterpret_cast<const uint2*>(g_xvh + (size_t)s1 * D) + lane);
            float a0 = ai_h + aj0 + s_aje[e0 * H + h];
            a0 = fmaxf(a0, NEG_SLOPE * a0);
            float w0 = __expf(a0);
            float a1 = ai_h + aj1 + s_aje[e1 * H + h];
            a1 = fmaxf(a1, NEG_SLOPE * a1);
            float w1 = __expf(a1);
            denom += w0;
            denom += w1;
            float4 v0 = h4_to_f4(h0);
            float4 v1 = h4_to_f4(h1);
            const float4 ee0 = *reinterpret_cast<const float4*>(&s_xve[e0 * D + lane * 4]);
            const float4 ee1 = *reinterpret_cast<const float4*>(&s_xve[e1 * D + lane * 4]);
            acc.x = fmaf(w0, v0.x + ee0.x, acc.x);
            acc.y = fmaf(w0, v0.y + ee0.y, acc.y);
            acc.z = fmaf(w0, v0.z + ee0.z, acc.z);
            acc.w = fmaf(w0, v0.w + ee0.w, acc.w);
            acc.x = fmaf(w1, v1.x + ee1.x, acc.x);
            acc.y = fmaf(w1, v1.y + ee1.y, acc.y);
            acc.z = fmaf(w1, v1.z + ee1.z, acc.z);
            acc.w = fmaf(w1, v1.w + ee1.w, acc.w);
        }
        if (j < cnt) {
            int p0 = __shfl_sync(0xFFFFFFFFu, p, j);
            int s0 = p0 & 0xFFFFFF, e0 = p0 >> 24;
            float aj0 = __ldg(&g_aj[s0 * H + h]);
            uint2 h0 = __ldg(reinterpret_cast<const uint2*>(g_xvh + (size_t)s0 * D) + lane);
            float a0 = ai_h + aj0 + s_aje[e0 * H + h];
            a0 = fmaxf(a0, NEG_SLOPE * a0);
            float w0 = __expf(a0);
            denom += w0;
            float4 v0 = h4_to_f4(h0);
            const float4 ee0 = *reinterpret_cast<const float4*>(&s_xve[e0 * D + lane * 4]);
            acc.x = fmaf(w0, v0.x + ee0.x, acc.x);
            acc.y = fmaf(w0, v0.y + ee0.y, acc.y);
            acc.z = fmaf(w0, v0.z + ee0.z, acc.z);
            acc.w = fmaf(w0, v0.w + ee0.w, acc.w);
        }
    }

    float inv = 1.f / (denom + 1e-16f);
    float4 b4 = __ldg(reinterpret_cast<const float4*>(bias) + lane);
    float4 r;
    r.x = fmaf(acc.x, inv, b4.x);
    r.y = fmaf(acc.y, inv, b4.y);
    r.z = fmaf(acc.z, inv, b4.z);
    r.w = fmaf(acc.w, inv, b4.w);
    reinterpret_cast<float4*>(out + (size_t)n * D)[lane] = r;
}

extern "C" void kernel_launch(void* const* d_in, const int* in_sizes, int n_in,
                              void* d_out, int out_size) {
    const float* x         = (const float*)d_in[0];
    const int*   ei        = (const int*)  d_in[1];
    const int*   node_type = (const int*)d_in[2];
    const int*   edge_type = (const int*)d_in[3];
    const float* Wq        = (const float*)d_in[4];
    const float* Wk        = (const float*)d_in[5];
    const float* Wv        = (const float*)d_in[6];
    const float* att_i     = (const float*)d_in[7];
    const float* att_j     = (const float*)d_in[8];
    const float* bias      = (const float*)d_in[9];
    const float* node_emb  = (const float*)d_in[10];
    const float* edge_emb  = (const float*)d_in[11];
    float* out = (float*)d_out;

    int N = in_sizes[2];
    int E = in_sizes[3];
    int nb = (N + SCAN_BLK - 1) / SCAN_BLK;

    // single stream, linear chain (graph-capture safe)
    zero_kernel<<<(N + 255) / 256, 256>>>(N);
    precompute_kernel<<<140, 128>>>(Wq, Wk, Wv, att_i, att_j, edge_emb);
    hist_kernel<<<(E + 255) / 256, 256>>>(ei, E);
    scan1_kernel<<<nb, SCAN_BLK>>>(N);
    scan2_kernel<<<1, 256>>>(nb, N);
    scan3_kernel<<<nb, SCAN_BLK>>>(N);
    scatter_kernel<<<(E + 255) / 256, 256>>>(ei, edge_type, E);
    node_kernel<<<(N + MTILE - 1) / MTILE, 128>>>(x, node_type, node_emb, N);
    gather_kernel<<<(N * 32 + 255) / 256, 256>>>(out, bias, N);
}

// round 11
// speedup vs baseline: 2.0153x; 1.1611x over previous
#include <cuda_runtime.h>
#include <cuda_fp16.h>
#include <math.h>

#define MAXN 40000
#define MAXE 640000
#define D 128
#define H 4
#define C 32
#define NEG_SLOPE 0.2f
#define SCAN_BLK 512

// -------- device scratch (static; no allocation allowed) --------
__device__ __half g_xvh[(size_t)MAXN * D];   // x' @ Wv^T per node (fp16, 10.2 MB)
__device__ float g_ai[MAXN * H];
__device__ float g_aj[MAXN * H];
__device__ float g_WvT[D * D];
__device__ float g_qvec[H * D];
__device__ float g_kvec[H * D];
__device__ float g_xv_edge[8 * D];
__device__ float g_aj_edge[8 * H];
__device__ int   g_deg[MAXN];
__device__ int   g_rowstart[MAXN + 1];
__device__ int   g_cursor[MAXN];
__device__ int   g_adj[MAXE];                // src | (et<<24)
__device__ int   g_bsum[256];
__device__ int   g_boff[256];

// ---- f32x2 helpers (sm_103a packed fp32 FMA) ----
__device__ __forceinline__ unsigned long long pack2(float x, float y) {
    unsigned long long r;
    asm("mov.b64 %0, {%1, %2};" : "=l"(r) : "f"(x), "f"(y));
    return r;
}
__device__ __forceinline__ void unpack2(unsigned long long v, float& x, float& y) {
    asm("mov.b64 {%0, %1}, %2;" : "=f"(x), "=f"(y) : "l"(v));
}
__device__ __forceinline__ void fma2(unsigned long long& acc, unsigned long long a,
                                     unsigned long long b) {
    asm("fma.rn.f32x2 %0, %1, %2, %0;" : "+l"(acc) : "l"(a), "l"(b));
}
__device__ __forceinline__ float4 h4_to_f4(uint2 u) {
    __half2 a = *reinterpret_cast<__half2*>(&u.x);
    __half2 b = *reinterpret_cast<__half2*>(&u.y);
    float2 fa = __half22float2(a);
    float2 fb = __half22float2(b);
    return make_float4(fa.x, fa.y, fb.x, fb.y);
}

// -------- widened precompute: grid = 140 blocks x 128 threads --------
__global__ void precompute_kernel(const float* __restrict__ Wq,
                                  const float* __restrict__ Wk,
                                  const float* __restrict__ Wv,
                                  const float* __restrict__ att_i,
                                  const float* __restrict__ att_j,
                                  const float* __restrict__ edge_emb) {
    int b = blockIdx.x, t = threadIdx.x;
    if (b < 4) {
        int h = b, d = t;
        float q = 0.f, k = 0.f;
        #pragma unroll
        for (int c = 0; c < C; c++) {
            q = fmaf(__ldg(&Wq[(h * C + c) * D + d]), __ldg(&att_i[h * C + c]), q);
            k = fmaf(__ldg(&Wk[(h * C + c) * D + d]), __ldg(&att_j[h * C + c]), k);
        }
        g_qvec[h * D + d] = q;
        g_kvec[h * D + d] = k;
        __shared__ float red[D];
        for (int et = 0; et < 8; et++) {
            red[t] = __ldg(&edge_emb[et * D + t]) * k;
            __syncthreads();
            for (int s = 64; s > 0; s >>= 1) {
                if (t < s) red[t] += red[t + s];
                __syncthreads();
            }
            if (t == 0) g_aj_edge[et * H + h] = red[0];
            __syncthreads();
        }
    } else if (b < 12) {
        int et = b - 4;
        float s = 0.f;
        for (int dd = 0; dd < D; dd++)
            s = fmaf(__ldg(&Wv[t * D + dd]), __ldg(&edge_emb[et * D + dd]), s);
        g_xv_edge[et * D + t] = s;
    } else {
        int i = (b - 12) * 128 + t;
        int d = i >> 7, o = i & 127;
        g_WvT[i] = __ldg(&Wv[o * D + d]);
    }
}

// -------- CSR build --------
__global__ void zero_kernel(int N) {
    int i = blockIdx.x * blockDim.x + threadIdx.x;
    if (i < N) g_deg[i] = 0;
}

__global__ void hist_kernel(const int* __restrict__ ei, int E) {
    int e = blockIdx.x * blockDim.x + threadIdx.x;
    if (e < E) atomicAdd(&g_deg[__ldg(&ei[E + e])], 1);
}

// phase 1: per-block local scan + block sums (full-warp shuffles only)
__global__ void scan1_kernel(int N) {
    __shared__ int ws[SCAN_BLK / 32];
    int t = threadIdx.x, lane = t & 31, wid = t >> 5;
    int idx = blockIdx.x * SCAN_BLK + t;
    int v = (idx < N) ? g_deg[idx] : 0;
    int s = v;
    #pragma unroll
    for (int o = 1; o < 32; o <<= 1) {
        int y = __shfl_up_sync(0xFFFFFFFFu, s, o);
        if (lane >= o) s += y;
    }
    if (lane == 31) ws[wid] = s;
    __syncthreads();
    if (wid == 0) {
        int wv = (lane < SCAN_BLK / 32) ? ws[lane] : 0;
        #pragma unroll
        for (int o = 1; o < SCAN_BLK / 32; o <<= 1) {
            int y = __shfl_up_sync(0xFFFFFFFFu, wv, o);
            if (lane >= o) wv += y;
        }
        if (lane < SCAN_BLK / 32) ws[lane] = wv;
    }
    __syncthreads();
    int base = (wid > 0) ? ws[wid - 1] : 0;
    if (idx < N) g_rowstart[idx] = base + s - v;
    if (t == 0) g_bsum[blockIdx.x] = ws[SCAN_BLK / 32 - 1];
}

// phase 2: scan the (<=256) block sums
__global__ void scan2_kernel(int nb, int N) {
    __shared__ int ws[8];
    int t = threadIdx.x, lane = t & 31, wid = t >> 5;  // 256 threads
    int v = (t < nb) ? g_bsum[t] : 0;
    int s = v;
    #pragma unroll
    for (int o = 1; o < 32; o <<= 1) {
        int y = __shfl_up_sync(0xFFFFFFFFu, s, o);
        if (lane >= o) s += y;
    }
    if (lane == 31) ws[wid] = s;
    __syncthreads();
    int add = 0;
    for (int w = 0; w < wid; w++) add += ws[w];
    s += add;
    if (t < nb) g_boff[t] = s - v;
    if (t == nb - 1) g_rowstart[N] = s;
}

// phase 3: add block offsets, init cursor
__global__ void scan3_kernel(int N) {
    int idx = blockIdx.x * SCAN_BLK + threadIdx.x;
    if (idx < N) {
        int r = g_rowstart[idx] + g_boff[blockIdx.x];
        g_rowstart[idx] = r;
        g_cursor[idx] = r;
    }
}

__global__ void scatter_kernel(const int* __restrict__ ei,
                               const int* __restrict__ edge_type, int E) {
    int e = blockIdx.x * blockDim.x + threadIdx.x;
    if (e < E) {
        int src = __ldg(&ei[e]);
        int dst = __ldg(&ei[E + e]);
        int et  = __ldg(&edge_type[e]);
        int pos = atomicAdd(&g_cursor[dst], 1);
        g_adj[pos] = src | (et << 24);
    }
}

// -------- per-node: x' = x + emb; xv = x'@Wv^T (f32x2); ai/aj --------
#define MTILE 16
__global__ void node_kernel(const float* __restrict__ x,
                            const int* __restrict__ node_type,
                            const float* __restrict__ node_emb, int N) {
    __shared__ float xs[D * 18];
    int t = threadIdx.x;          // 128
    int base = blockIdx.x * MTILE;
    #pragma unroll
    for (int m = 0; m < MTILE; m++) {
        int n = base + m;
        float val = 0.f;
        if (n < N) {
            int nt = __ldg(&node_type[n]);
            val = __ldg(&x[(size_t)n * D + t]) + __ldg(&node_emb[nt * D + t]);
        }
        xs[t * 18 + m] = val;
    }
    __syncthreads();

    unsigned long long acc2[8];
    #pragma unroll
    for (int i = 0; i < 8; i++) acc2[i] = pack2(0.f, 0.f);

    #pragma unroll 4
    for (int d = 0; d < D; d++) {
        float w = g_WvT[d * D + t];
        unsigned long long ww = pack2(w, w);
        const float2* xr = reinterpret_cast<const float2*>(&xs[d * 18]);
        #pragma unroll
        for (int i = 0; i < 8; i++) {
            float2 xp = xr[i];
            unsigned long long xp2 = *reinterpret_cast<unsigned long long*>(&xp);
            fma2(acc2[i], xp2, ww);
        }
    }
    #pragma unroll
    for (int i = 0; i < 8; i++) {
        float lo, hi;
        unpack2(acc2[i], lo, hi);
        int n0 = base + 2 * i;
        if (n0 < N)     g_xvh[(size_t)n0 * D + t]       = __float2half(lo);
        if (n0 + 1 < N) g_xvh[(size_t)(n0 + 1) * D + t] = __float2half(hi);
    }

    if (t < 64) {
        int m = t >> 2, h = t & 3;
        int n = base + m;
        if (n < N) {
            float ai = 0.f, aj = 0.f;
            for (int d = 0; d < D; d++) {
                float xv = xs[d * 18 + m];
                ai = fmaf(xv, g_qvec[h * D + d], ai);
                aj = fmaf(xv, g_kvec[h * D + d], aj);
            }
            g_ai[n * H + h] = ai;
            g_aj[n * H + h] = aj;
        }
    }
}

// -------- gather: one warp per dst node, 4x unrolled for MLP --------
__global__ void gather_kernel(float* __restrict__ out,
                              const float* __restrict__ bias, int N) {
    __shared__ float s_xve[8 * D];
    __shared__ float s_aje[8 * H];
    int tid = threadIdx.x;
    for (int i = tid; i < 8 * D; i += blockDim.x) s_xve[i] = g_xv_edge[i];
    if (tid < 32) s_aje[tid] = g_aj_edge[tid];
    __syncthreads();

    int n = (blockIdx.x * blockDim.x + tid) >> 5;
    int lane = tid & 31;
    if (n >= N) return;
    int h = lane >> 3;

    float ai_h = __ldg(&g_ai[n * H + h]);

    // self-loop (edge type 0)
    float a = ai_h + __ldg(&g_aj[n * H + h]) + s_aje[h];
    a = fmaxf(a, NEG_SLOPE * a);
    float w = __expf(a);
    float denom = w;
    uint2 hv = __ldg(reinterpret_cast<const uint2*>(g_xvh + (size_t)n * D) + lane);
    float4 v = h4_to_f4(hv);
    float4 ev = *reinterpret_cast<const float4*>(&s_xve[lane * 4]);
    float4 acc;
    acc.x = w * (v.x + ev.x);
    acc.y = w * (v.y + ev.y);
    acc.z = w * (v.z + ev.z);
    acc.w = w * (v.w + ev.w);

    int row0 = __ldg(&g_rowstart[n]);
    int row1 = __ldg(&g_rowstart[n + 1]);
    for (int bs = row0; bs < row1; bs += 32) {
        int rem = row1 - bs;
        int cnt = min(rem, 32);
        int p = (lane < cnt) ? __ldg(&g_adj[bs + lane]) : 0;
        int j = 0;
        // 4-wide: issue all gathers up front for MLP
        for (; j + 3 < cnt; j += 4) {
            int p0 = __shfl_sync(0xFFFFFFFFu, p, j);
            int p1 = __shfl_sync(0xFFFFFFFFu, p, j + 1);
            int p2 = __shfl_sync(0xFFFFFFFFu, p, j + 2);
            int p3 = __shfl_sync(0xFFFFFFFFu, p, j + 3);
            int s0 = p0 & 0xFFFFFF, e0 = p0 >> 24;
            int s1 = p1 & 0xFFFFFF, e1 = p1 >> 24;
            int s2 = p2 & 0xFFFFFF, e2 = p2 >> 24;
            int s3 = p3 & 0xFFFFFF, e3 = p3 >> 24;
            float aj0 = __ldg(&g_aj[s0 * H + h]);
            float aj1 = __ldg(&g_aj[s1 * H + h]);
            float aj2 = __ldg(&g_aj[s2 * H + h]);
            float aj3 = __ldg(&g_aj[s3 * H + h]);
            uint2 h0 = __ldg(reinterpret_cast<const uint2*>(g_xvh + (size_t)s0 * D) + lane);
            uint2 h1 = __ldg(reinterpret_cast<const uint2*>(g_xvh + (size_t)s1 * D) + lane);
            uint2 h2 = __ldg(reinterpret_cast<const uint2*>(g_xvh + (size_t)s2 * D) + lane);
            uint2 h3 = __ldg(reinterpret_cast<const uint2*>(g_xvh + (size_t)s3 * D) + lane);
            float a0 = ai_h + aj0 + s_aje[e0 * H + h];
            float a1 = ai_h + aj1 + s_aje[e1 * H + h];
            float a2 = ai_h + aj2 + s_aje[e2 * H + h];
            float a3 = ai_h + aj3 + s_aje[e3 * H + h];
            a0 = fmaxf(a0, NEG_SLOPE * a0);
            a1 = fmaxf(a1, NEG_SLOPE * a1);
            a2 = fmaxf(a2, NEG_SLOPE * a2);
            a3 = fmaxf(a3, NEG_SLOPE * a3);
            float w0 = __expf(a0), w1 = __expf(a1);
            float w2 = __expf(a2), w3 = __expf(a3);
            denom += w0; denom += w1; denom += w2; denom += w3;
            float4 v0 = h4_to_f4(h0);
            float4 v1 = h4_to_f4(h1);
            float4 v2 = h4_to_f4(h2);
            float4 v3 = h4_to_f4(h3);
            const float4 ee0 = *reinterpret_cast<const float4*>(&s_xve[e0 * D + lane * 4]);
            const float4 ee1 = *reinterpret_cast<const float4*>(&s_xve[e1 * D + lane * 4]);
            const float4 ee2 = *reinterpret_cast<const float4*>(&s_xve[e2 * D + lane * 4]);
            const float4 ee3 = *reinterpret_cast<const float4*>(&s_xve[e3 * D + lane * 4]);
            acc.x = fmaf(w0, v0.x + ee0.x, acc.x);
            acc.y = fmaf(w0, v0.y + ee0.y, acc.y);
            acc.z = fmaf(w0, v0.z + ee0.z, acc.z);
            acc.w = fmaf(w0, v0.w + ee0.w, acc.w);
            acc.x = fmaf(w1, v1.x + ee1.x, acc.x);
            acc.y = fmaf(w1, v1.y + ee1.y, acc.y);
            acc.z = fmaf(w1, v1.z + ee1.z, acc.z);
            acc.w = fmaf(w1, v1.w + ee1.w, acc.w);
            acc.x = fmaf(w2, v2.x + ee2.x, acc.x);
            acc.y = fmaf(w2, v2.y + ee2.y, acc.y);
            acc.z = fmaf(w2, v2.z + ee2.z, acc.z);
            acc.w = fmaf(w2, v2.w + ee2.w, acc.w);
            acc.x = fmaf(w3, v3.x + ee3.x, acc.x);
            acc.y = fmaf(w3, v3.y + ee3.y, acc.y);
            acc.z = fmaf(w3, v3.z + ee3.z, acc.z);
            acc.w = fmaf(w3, v3.w + ee3.w, acc.w);
        }
        for (; j < cnt; j++) {
            int p0 = __shfl_sync(0xFFFFFFFFu, p, j);
            int s0 = p0 & 0xFFFFFF, e0 = p0 >> 24;
            float aj0 = __ldg(&g_aj[s0 * H + h]);
            uint2 h0 = __ldg(reinterpret_cast<const uint2*>(g_xvh + (size_t)s0 * D) + lane);
            float a0 = ai_h + aj0 + s_aje[e0 * H + h];
            a0 = fmaxf(a0, NEG_SLOPE * a0);
            float w0 = __expf(a0);
            denom += w0;
            float4 v0 = h4_to_f4(h0);
            const float4 ee0 = *reinterpret_cast<const float4*>(&s_xve[e0 * D + lane * 4]);
            acc.x = fmaf(w0, v0.x + ee0.x, acc.x);
            acc.y = fmaf(w0, v0.y + ee0.y, acc.y);
            acc.z = fmaf(w0, v0.z + ee0.z, acc.z);
            acc.w = fmaf(w0, v0.w + ee0.w, acc.w);
        }
    }

    float inv = 1.f / (denom + 1e-16f);
    float4 b4 = __ldg(reinterpret_cast<const float4*>(bias) + lane);
    float4 r;
    r.x = fmaf(acc.x, inv, b4.x);
    r.y = fmaf(acc.y, inv, b4.y);
    r.z = fmaf(acc.z, inv, b4.z);
    r.w = fmaf(acc.w, inv, b4.w);
    reinterpret_cast<float4*>(out + (size_t)n * D)[lane] = r;
}

extern "C" void kernel_launch(void* const* d_in, const int* in_sizes, int n_in,
                              void* d_out, int out_size) {
    const float* x         = (const float*)d_in[0];
    const int*   ei        = (const int*)  d_in[1];
    const int*   node_type = (const int*)d_in[2];
    const int*   edge_type = (const int*)d_in[3];
    const float* Wq        = (const float*)d_in[4];
    const float* Wk        = (const float*)d_in[5];
    const float* Wv        = (const float*)d_in[6];
    const float* att_i     = (const float*)d_in[7];
    const float* att_j     = (const float*)d_in[8];
    const float* bias      = (const float*)d_in[9];
    const float* node_emb  = (const float*)d_in[10];
    const float* edge_emb  = (const float*)d_in[11];
    float* out = (float*)d_out;

    int N = in_sizes[2];
    int E = in_sizes[3];
    int nb = (N + SCAN_BLK - 1) / SCAN_BLK;

    // fork capture: branch B (precompute -> node GEMM) parallel to CSR build.
    // Default-stream launches are captured, so ev-record on stream 0 is a
    // captured node and the fork/join is capture-legal.
    cudaStream_t s2;
    cudaEvent_t evFork, evJoin;
    cudaStreamCreateWithFlags(&s2, cudaStreamNonBlocking);
    cudaEventCreateWithFlags(&evFork, cudaEventDisableTiming);
    cudaEventCreateWithFlags(&evJoin, cudaEventDisableTiming);

    cudaEventRecord(evFork, 0);
    cudaStreamWaitEvent(s2, evFork, 0);
    precompute_kernel<<<140, 128, 0, s2>>>(Wq, Wk, Wv, att_i, att_j, edge_emb);
    node_kernel<<<(N + MTILE - 1) / MTILE, 128, 0, s2>>>(x, node_type, node_emb, N);
    cudaEventRecord(evJoin, s2);

    // branch A: CSR build on capture stream
    zero_kernel<<<(N + 255) / 256, 256>>>(N);
    hist_kernel<<<(E + 255) / 256, 256>>>(ei, E);
    scan1_kernel<<<nb, SCAN_BLK>>>(N);
    scan2_kernel<<<1, 256>>>(nb, N);
    scan3_kernel<<<nb, SCAN_BLK>>>(N);
    scatter_kernel<<<(E + 255) / 256, 256>>>(ei, edge_type, E);

    // join, then gather
    cudaStreamWaitEvent(0, evJoin, 0);
    gather_kernel<<<(N * 32 + 255) / 256, 256>>>(out, bias, N);
}